// round 8
// baseline (speedup 1.0000x reference)
#include <cuda_runtime.h>
#include <cstdint>

#define H_DIM 2048
#define I_DIM 1024
#define NEXP  8
#define T_TOK 2048
#define NSLOT 4096   // T_TOK * TOPK

// ---------------- static device scratch -------------------------------------
__device__ int   d_counts[NEXP];
__device__ int   d_list[NEXP * NSLOT];
__device__ int   d_use32;
__device__ float d_act[(size_t)NSLOT * I_DIM];    // 16 MB (tf32-rounded)
__device__ float d_xr[(size_t)T_TOK * H_DIM];     // 16 MB x, tf32-rounded

// ---------------- portable PTX helpers --------------------------------------
__device__ __forceinline__ uint32_t smem_u32(const void* p) {
    uint32_t a;
    asm("{ .reg .u64 t; cvta.to.shared.u64 t, %1; cvt.u32.u64 %0, t; }"
        : "=r"(a) : "l"(p));
    return a;
}
__device__ __forceinline__ void cp16(uint32_t dst, const void* src) {
    asm volatile("cp.async.cg.shared.global [%0], [%1], 16;"
                 :: "r"(dst), "l"(src) : "memory");
}
#define CP_COMMIT() asm volatile("cp.async.commit_group;" ::: "memory")
#define CP_WAIT0()  asm volatile("cp.async.wait_group 0;" ::: "memory")
#define CP_WAIT1()  asm volatile("cp.async.wait_group 1;" ::: "memory")

__device__ __forceinline__ void ldsm4(uint32_t* r, uint32_t addr) {
    asm volatile("ldmatrix.sync.aligned.m8n8.x4.shared.b16 {%0,%1,%2,%3}, [%4];"
                 : "=r"(r[0]), "=r"(r[1]), "=r"(r[2]), "=r"(r[3]) : "r"(addr));
}
__device__ __forceinline__ void mma_tf32(float* c, const uint32_t* a, const uint32_t* b) {
    asm volatile("mma.sync.aligned.m16n8k8.row.col.f32.tf32.tf32.f32 "
                 "{%0,%1,%2,%3}, {%4,%5,%6,%7}, {%8,%9}, {%0,%1,%2,%3};"
                 : "+f"(c[0]), "+f"(c[1]), "+f"(c[2]), "+f"(c[3])
                 : "r"(a[0]), "r"(a[1]), "r"(a[2]), "r"(a[3]),
                   "r"(b[0]), "r"(b[1]));
}
__device__ __forceinline__ uint32_t rna(uint32_t bits) {
    uint32_t u;
    asm("cvt.rna.tf32.f32 %0, %1;" : "=r"(u) : "f"(__uint_as_float(bits)));
    return u;
}
__device__ __forceinline__ float rnaf(float f) {
    uint32_t u;
    asm("cvt.rna.tf32.f32 %0, %1;" : "=r"(u) : "f"(f));
    return __uint_as_float(u);
}
__device__ __forceinline__ void redadd(float* p, float v) {
    asm volatile("red.global.add.f32 [%0], %1;" :: "l"(p), "f"(v) : "memory");
}

// ---------------- routing / prep ---------------------------------------------
__global__ void k_prep(const int* __restrict__ idx32) {
    __shared__ int found;
    if (threadIdx.x == 0) found = 0;
    if (threadIdx.x < NEXP) d_counts[threadIdx.x] = 0;
    __syncthreads();
    int f = 0;
    for (int i = threadIdx.x; i < T_TOK; i += blockDim.x)
        if (idx32[2 * i + 1] != 0) f = 1;
    if (f) atomicOr(&found, 1);
    __syncthreads();
    if (threadIdx.x == 0) d_use32 = found;
}
__global__ void k_route(const int* __restrict__ idx32) {
    int s = blockIdx.x * 256 + threadIdx.x;
    if (s < NSLOT) {
        int e = d_use32 ? idx32[s] : idx32[2 * s];
        int p = atomicAdd(&d_counts[e], 1);
        d_list[e * NSLOT + p] = s;
    }
}
__global__ void k_cvtx(const float4* __restrict__ s, float4* __restrict__ d, int n4) {
    int i = blockIdx.x * blockDim.x + threadIdx.x;
    if (i < n4) {
        float4 v = s[i];
        float4 o;
        o.x = rnaf(v.x); o.y = rnaf(v.y); o.z = rnaf(v.z); o.w = rnaf(v.w);
        d[i] = o;
    }
}
__global__ void k_zero(float4* __restrict__ o, int n4) {
    int i = blockIdx.x * blockDim.x + threadIdx.x;
    if (i < n4) o[i] = make_float4(0.f, 0.f, 0.f, 0.f);
}

// ============================================================================
// Tiling: CTA 64(M) x 128(N), BK=32 (128B rows), swizzle granule g^(row&7).
// ldmatrix lane map: li = lane>>3, lj = lane&7.
// A x4: row += (li&1)*8, delta16 = (li>>1)*16
// B x4: row += (li>>1)*8, delta16 = (li&1)*16
// addr = tile + row*128 + (((ck*32)|delta16) ^ (lj*16))
// ============================================================================
#define A_TILE_B  8192               // 64 rows * 128 B
#define B_TILE_B  16384              // 128 rows * 128 B
#define G1_STAGE  (A_TILE_B + 2 * B_TILE_B)   // A, G, U = 40960
#define G1_SMEM   (512 + 2 * G1_STAGE)        // 2-stage, 82432
#define G2_STAGE  (A_TILE_B + B_TILE_B)       // A, B = 24576
#define G2_SMEM   (512 + 3 * G2_STAGE)        // 3-stage, 74240

// ---------------- GEMM1: gate+up, 256 thr, 2 CTA/SM, 2-stage -----------------
__global__ __launch_bounds__(256, 2) void k_gu(
    const float* __restrict__ gate, const float* __restrict__ up,
    const float* __restrict__ wts) {

    extern __shared__ char smem[];
    const int e   = blockIdx.z;
    const int cnt = d_counts[e];
    const int m0  = blockIdx.x * 64;
    if (m0 >= cnt) return;
    const int n0  = blockIdx.y * 128;
    const int tid = threadIdx.x;

    int* Srow = (int*)smem;
    if (tid < 64) {
        int m = m0 + tid;
        Srow[tid] = d_list[e * NSLOT + (m < cnt ? m : m0)];
    }
    __syncthreads();

    const uint32_t sb = smem_u32(smem);

    // A cp: row = tid>>2 (0..63), 2 granules.  B cp: row = tid>>1 (0..127), 4 granules.
    const int ra  = tid >> 2, ca = tid & 3;
    const int rb  = tid >> 1, cb = tid & 1;
    const float* aP = d_xr + (size_t)(Srow[ra] >> 1) * H_DIM + ca * 8;
    const float* gP = gate + ((size_t)e * I_DIM + n0 + rb) * H_DIM + cb * 16;
    const float* uP = up   + ((size_t)e * I_DIM + n0 + rb) * H_DIM + cb * 16;
    uint32_t dA[2], dG[4], dU[4];
#pragma unroll
    for (int j = 0; j < 2; j++) {
        uint32_t gsw = (uint32_t)((ca * 2 + j) ^ (ra & 7));
        dA[j] = (uint32_t)ra * 128 + gsw * 16;
    }
#pragma unroll
    for (int j = 0; j < 4; j++) {
        uint32_t gsw = (uint32_t)((cb * 4 + j) ^ (rb & 7));
        uint32_t o   = (uint32_t)rb * 128 + gsw * 16;
        dG[j] = A_TILE_B + o; dU[j] = A_TILE_B + B_TILE_B + o;
    }

    const int lane = tid & 31, wid = tid >> 5;      // 8 warps: 2M x 4N
    const int wm = wid & 1, wn = wid >> 1;
    const int lr = lane >> 2, lc = lane & 3;
    const int li = lane >> 3, lj = lane & 7;
    const uint32_t j16  = (uint32_t)lj * 16;
    const uint32_t dltA = (uint32_t)(li >> 1) * 16;
    const uint32_t dltB = (uint32_t)(li & 1) * 16;
    uint32_t preA[2], preB[2];
#pragma unroll
    for (int mf = 0; mf < 2; mf++)
        preA[mf] = (uint32_t)(wm * 32 + mf * 16 + (li & 1) * 8 + lj) * 128;
#pragma unroll
    for (int p = 0; p < 2; p++)
        preB[p] = (uint32_t)(wn * 32 + p * 16 + (li >> 1) * 8 + lj) * 128;

    float Cg[2][4][4] = {}, Cu[2][4][4] = {};
    const int NIT = H_DIM / 32;

#pragma unroll
    for (int pit = 0; pit < 2; pit++) {
        uint32_t base = sb + 512 + pit * G1_STAGE;
        int kb = pit * 32;
#pragma unroll
        for (int j = 0; j < 2; j++) cp16(base + dA[j], aP + kb + j * 4);
#pragma unroll
        for (int j = 0; j < 4; j++) {
            cp16(base + dG[j], gP + kb + j * 4);
            cp16(base + dU[j], uP + kb + j * 4);
        }
        CP_COMMIT();
    }

    for (int it = 0; it < NIT; ++it) {
        if (it < NIT - 1) CP_WAIT1(); else CP_WAIT0();
        __syncthreads();

        const int buf = it & 1;
        const uint32_t tA = sb + 512 + buf * G1_STAGE;
        const uint32_t tG = tA + A_TILE_B;
        const uint32_t tU = tG + B_TILE_B;
#pragma unroll
        for (int ck = 0; ck < 4; ck++) {
            const uint32_t xc  = (uint32_t)ck * 32;
            const uint32_t swA = (xc | dltA) ^ j16;
            const uint32_t swB = (xc | dltB) ^ j16;
            uint32_t a[2][4];
#pragma unroll
            for (int mf = 0; mf < 2; mf++)
                ldsm4(a[mf], tA + preA[mf] + swA);       // x pre-rounded
            uint32_t bg[2][4], bu[2][4];
#pragma unroll
            for (int p = 0; p < 2; p++) {
                ldsm4(bg[p], tG + preB[p] + swB);
                ldsm4(bu[p], tU + preB[p] + swB);
#pragma unroll
                for (int q = 0; q < 4; q++) {
                    bg[p][q] = rna(bg[p][q]);
                    bu[p][q] = rna(bu[p][q]);
                }
            }
#pragma unroll
            for (int mf = 0; mf < 2; mf++)
#pragma unroll
                for (int nf = 0; nf < 4; nf++) {
                    mma_tf32(Cg[mf][nf], a[mf], &bg[nf >> 1][(nf & 1) * 2]);
                    mma_tf32(Cu[mf][nf], a[mf], &bu[nf >> 1][(nf & 1) * 2]);
                }
        }

        if (it + 2 < NIT) {
            __syncthreads();                 // everyone done reading buf
            uint32_t base = sb + 512 + buf * G1_STAGE;
            int kb = (it + 2) * 32;
#pragma unroll
            for (int j = 0; j < 2; j++) cp16(base + dA[j], aP + kb + j * 4);
#pragma unroll
            for (int j = 0; j < 4; j++) {
                cp16(base + dG[j], gP + kb + j * 4);
                cp16(base + dU[j], uP + kb + j * 4);
            }
            CP_COMMIT();
        }
    }

    // epilogue: silu(g)*u*w -> d_act (tf32-rounded)
#pragma unroll
    for (int mf = 0; mf < 2; mf++) {
#pragma unroll
        for (int h = 0; h < 2; h++) {
            int mrow = wm * 32 + mf * 16 + lr + h * 8;
            bool ok  = (m0 + mrow) < cnt;
            int slot = Srow[mrow];
            float w  = ok ? wts[slot] : 0.0f;
            float* dst = d_act + (size_t)slot * I_DIM + n0 + wn * 32 + 2 * lc;
            if (ok) {
#pragma unroll
                for (int nf = 0; nf < 4; nf++) {
                    float g0v = Cg[mf][nf][2 * h],     u0v = Cu[mf][nf][2 * h];
                    float g1v = Cg[mf][nf][2 * h + 1], u1v = Cu[mf][nf][2 * h + 1];
                    float2 o;
                    o.x = rnaf((g0v / (1.0f + __expf(-g0v))) * u0v * w);
                    o.y = rnaf((g1v / (1.0f + __expf(-g1v))) * u1v * w);
                    *(float2*)(dst + nf * 8) = o;
                }
            }
        }
    }
}

// ---------------- GEMM2: down, 256 thr, 2 CTA/SM, 3-stage single-sync --------
__global__ __launch_bounds__(256, 2) void k_dn(const float* __restrict__ down,
                                               float* __restrict__ out) {
    extern __shared__ char smem[];
    const int e   = blockIdx.z;
    const int cnt = d_counts[e];
    const int m0  = blockIdx.x * 64;
    if (m0 >= cnt) return;
    const int n0  = blockIdx.y * 128;
    const int tid = threadIdx.x;

    int* Srow = (int*)smem;
    if (tid < 64) {
        int m = m0 + tid;
        Srow[tid] = d_list[e * NSLOT + (m < cnt ? m : m0)];
    }
    __syncthreads();

    const uint32_t sb = smem_u32(smem);

    const int ra = tid >> 2, ca = tid & 3;
    const int rb = tid >> 1, cb = tid & 1;
    const float* aP = d_act + (size_t)Srow[ra] * I_DIM + ca * 8;
    const float* bP = down  + ((size_t)e * H_DIM + n0 + rb) * I_DIM + cb * 16;
    uint32_t dA[2], dB[4];
#pragma unroll
    for (int j = 0; j < 2; j++) {
        uint32_t gsw = (uint32_t)((ca * 2 + j) ^ (ra & 7));
        dA[j] = (uint32_t)ra * 128 + gsw * 16;
    }
#pragma unroll
    for (int j = 0; j < 4; j++) {
        uint32_t gsw = (uint32_t)((cb * 4 + j) ^ (rb & 7));
        dB[j] = A_TILE_B + (uint32_t)rb * 128 + gsw * 16;
    }

    const int lane = tid & 31, wid = tid >> 5;      // 8 warps: 2M x 4N
    const int wm = wid & 1, wn = wid >> 1;
    const int lr = lane >> 2, lc = lane & 3;
    const int li = lane >> 3, lj = lane & 7;
    const uint32_t j16  = (uint32_t)lj * 16;
    const uint32_t dltA = (uint32_t)(li >> 1) * 16;
    const uint32_t dltB = (uint32_t)(li & 1) * 16;
    uint32_t preA[2], preB[2];
#pragma unroll
    for (int mf = 0; mf < 2; mf++)
        preA[mf] = (uint32_t)(wm * 32 + mf * 16 + (li & 1) * 8 + lj) * 128;
#pragma unroll
    for (int p = 0; p < 2; p++)
        preB[p] = (uint32_t)(wn * 32 + p * 16 + (li >> 1) * 8 + lj) * 128;

    float C[2][4][4] = {};
    const int NIT = I_DIM / 32;

#pragma unroll
    for (int pit = 0; pit < 2; pit++) {
        uint32_t base = sb + 512 + pit * G2_STAGE;
        int kb = pit * 32;
#pragma unroll
        for (int j = 0; j < 2; j++) cp16(base + dA[j], aP + kb + j * 4);
#pragma unroll
        for (int j = 0; j < 4; j++) cp16(base + dB[j], bP + kb + j * 4);
        CP_COMMIT();
    }

    int buf = 0;
    for (int it = 0; it < NIT; ++it) {
        if (it < NIT - 1) CP_WAIT1(); else CP_WAIT0();
        __syncthreads();

        if (it + 2 < NIT) {              // fills buffer last read at it-1
            uint32_t base = sb + 512 + ((it + 2) % 3) * G2_STAGE;
            int kb = (it + 2) * 32;
#pragma unroll
            for (int j = 0; j < 2; j++) cp16(base + dA[j], aP + kb + j * 4);
#pragma unroll
            for (int j = 0; j < 4; j++) cp16(base + dB[j], bP + kb + j * 4);
            CP_COMMIT();
        }

        const uint32_t tA = sb + 512 + buf * G2_STAGE;
        const uint32_t tB = tA + A_TILE_B;
#pragma unroll
        for (int ck = 0; ck < 4; ck++) {
            const uint32_t xc  = (uint32_t)ck * 32;
            const uint32_t swA = (xc | dltA) ^ j16;
            const uint32_t swB = (xc | dltB) ^ j16;
            uint32_t a[2][4];
#pragma unroll
            for (int mf = 0; mf < 2; mf++)
                ldsm4(a[mf], tA + preA[mf] + swA);       // act pre-rounded
            uint32_t b[2][4];
#pragma unroll
            for (int p = 0; p < 2; p++) {
                ldsm4(b[p], tB + preB[p] + swB);
#pragma unroll
                for (int q = 0; q < 4; q++) b[p][q] = rna(b[p][q]);
            }
#pragma unroll
            for (int mf = 0; mf < 2; mf++)
#pragma unroll
                for (int nf = 0; nf < 4; nf++)
                    mma_tf32(C[mf][nf], a[mf], &b[nf >> 1][(nf & 1) * 2]);
        }
        buf = (buf + 1 == 3) ? 0 : buf + 1;
    }

#pragma unroll
    for (int mf = 0; mf < 2; mf++) {
#pragma unroll
        for (int h = 0; h < 2; h++) {
            int mrow = wm * 32 + mf * 16 + lr + h * 8;
            bool ok  = (m0 + mrow) < cnt;
            int slot = Srow[mrow];
            if (ok) {
                int tok = slot >> 1;
                float* dst = out + (size_t)tok * H_DIM + n0 + wn * 32 + 2 * lc;
#pragma unroll
                for (int nf = 0; nf < 4; nf++) {
                    redadd(dst + nf * 8,     C[mf][nf][2 * h]);
                    redadd(dst + nf * 8 + 1, C[mf][nf][2 * h + 1]);
                }
            }
        }
    }
}

// ---------------- launch -----------------------------------------------------
extern "C" void kernel_launch(void* const* d_in, const int* in_sizes, int n_in,
                              void* d_out, int out_size) {
    const float* x    = (const float*)d_in[0];
    const int*   idx  = (const int*)  d_in[1];
    const float* wts  = (const float*)d_in[2];
    const float* gate = (const float*)d_in[3];
    const float* up   = (const float*)d_in[4];
    const float* down = (const float*)d_in[5];
    float*       out  = (float*)d_out;

    cudaFuncSetAttribute(k_gu, cudaFuncAttributeMaxDynamicSharedMemorySize, G1_SMEM);
    cudaFuncSetAttribute(k_dn, cudaFuncAttributeMaxDynamicSharedMemorySize, G2_SMEM);

    k_prep<<<1, 1024>>>(idx);
    k_route<<<NSLOT / 256, 256>>>(idx);

    float* xr;
    cudaGetSymbolAddress((void**)&xr, d_xr);
    int n4x = T_TOK * H_DIM / 4;
    k_cvtx<<<(n4x + 255) / 256, 256>>>((const float4*)x, (float4*)xr, n4x);
    k_zero<<<(n4x + 255) / 256, 256>>>((float4*)out, n4x);

    dim3 g1(NSLOT / 64, I_DIM / 128, NEXP);
    k_gu<<<g1, 256, G1_SMEM>>>(gate, up, wts);

    dim3 g2(NSLOT / 64, H_DIM / 128, NEXP);
    k_dn<<<g2, 256, G2_SMEM>>>(down, out);
}